// round 5
// baseline (speedup 1.0000x reference)
#include <cuda_runtime.h>
#include <cstdint>

// ---------------------------------------------------------------------------
// RNG mapping (verified R1, rel_err 5.4e-8): threefry_partitionable,
// bits[i] = x0 ^ x1 of threefry2x32(key=(0,42), ctr=(0,i)), keep = (bits>>9) < 838861
// ---------------------------------------------------------------------------
static constexpr int Bc = 4, Hc = 16, Sc = 2048, Dc = 64;
static constexpr int QT = 128, KT = 128;
static constexpr int NT = 256;

// smem layout (floats): Q[128][64] | Kt[64][128] swizzled | V[128][64] | P[128][128]
static constexpr int SQ_OFF = 0;
static constexpr int SK_OFF = SQ_OFF + QT * Dc;     // 8192
static constexpr int SV_OFF = SK_OFF + Dc * KT;     // 16384
static constexpr int SP_OFF = SV_OFF + KT * Dc;     // 24576
static constexpr int SMEM_FLOATS = SP_OFF + QT * KT; // 40960 -> 160KB

typedef unsigned long long u64;

__device__ __forceinline__ void threefry2x32(uint32_t c0, uint32_t c1,
                                             uint32_t& o0, uint32_t& o1)
{
    const uint32_t K0 = 0u, K1 = 42u;
    const uint32_t K2 = 0x1BD11BDAu ^ K0 ^ K1;
    uint32_t x0 = c0 + K0;
    uint32_t x1 = c1 + K1;
#define TF_R(r) { x0 += x1; x1 = __funnelshift_l(x1, x1, (r)); x1 ^= x0; }
    TF_R(13) TF_R(15) TF_R(26) TF_R(6)
    x0 += K1; x1 += K2 + 1u;
    TF_R(17) TF_R(29) TF_R(16) TF_R(24)
    x0 += K2; x1 += K0 + 2u;
    TF_R(13) TF_R(15) TF_R(26) TF_R(6)
    x0 += K0; x1 += K1 + 3u;
    TF_R(17) TF_R(29) TF_R(16) TF_R(24)
    x0 += K1; x1 += K2 + 4u;
    TF_R(13) TF_R(15) TF_R(26) TF_R(6)
    x0 += K2; x1 += K0 + 5u;
#undef TF_R
    o0 = x0; o1 = x1;
}

__device__ __forceinline__ bool keep_mask(uint32_t bh, uint32_t gq, uint32_t gk)
{
    uint32_t i = (bh << 22) | (gq << 11) | gk;
    uint32_t b0, b1;
    threefry2x32(0u, i, b0, b1);
    return ((b0 ^ b1) >> 9) < 838861u;
}

// ---- f32x2 packed math (sm_103a double-rate fp32) -------------------------
__device__ __forceinline__ u64 dup2(float x)
{ u64 r; asm("mov.b64 %0, {%1, %1};" : "=l"(r) : "f"(x)); return r; }
__device__ __forceinline__ void fma2(u64& d, u64 a, u64 b)
{ asm("fma.rn.f32x2 %0, %1, %2, %0;" : "+l"(d) : "l"(a), "l"(b)); }
__device__ __forceinline__ u64 mul2(u64 a, u64 b)
{ u64 r; asm("mul.rn.f32x2 %0, %1, %2;" : "=l"(r) : "l"(a), "l"(b)); return r; }
__device__ __forceinline__ void unpack2(u64 v, float& lo, float& hi)
{ asm("mov.b64 {%0, %1}, %2;" : "=f"(lo), "=f"(hi) : "l"(v)); }

__device__ __forceinline__ float f4c(const float4 v, int t)
{ return t == 0 ? v.x : t == 1 ? v.y : t == 2 ? v.z : v.w; }

__global__ void __launch_bounds__(NT, 1)
attn_kernel(const float* __restrict__ gq, const float* __restrict__ gk,
            const float* __restrict__ gv, float* __restrict__ gout)
{
    extern __shared__ float sm[];
    float* sQ = sm + SQ_OFF;
    float* sK = sm + SK_OFF;   // transposed [d][k], XOR-swizzled granules
    float* sV = sm + SV_OFF;   // natural [k][d]
    float* sP = sm + SP_OFF;   // natural [q][k], warp-private 16-row slabs

    const int tid = threadIdx.x;
    const int ty = tid >> 4;          // 0..15 -> 8 q-rows each
    const int tx = tid & 15;          // 0..15 -> k-cols {4tx..} U {64+4tx..}
    const int rowb = ty * 8;
    // 16-lane member mask for intra-half reductions (halves can diverge!)
    const uint32_t hm = (tid & 16) ? 0xffff0000u : 0x0000ffffu;
    const uint32_t bh = blockIdx.y;
    const int q0 = blockIdx.x * QT;

    const float* qb  = gq + ((size_t)bh * Sc + q0) * Dc;
    const float* kb0 = gk + (size_t)bh * Sc * Dc;
    const float* vb0 = gv + (size_t)bh * Sc * Dc;

    // ---- load Q tile (pre-scaled by sqrt(D)=8) ----
#pragma unroll
    for (int it = 0; it < 8; ++it) {
        int idx = tid + it * NT;
        int row = idx >> 4, c4 = (idx & 15) << 2;
        float4 v = *(const float4*)(qb + row * Dc + c4);
        v.x *= 8.f; v.y *= 8.f; v.z *= 8.f; v.w *= 8.f;
        *(float4*)&sQ[row * Dc + c4] = v;
    }

    u64 o2[8][2];
    float m[8], l[8];
#pragma unroll
    for (int r = 0; r < 8; ++r) {
        o2[r][0] = 0ull; o2[r][1] = 0ull;
        m[r] = -1e30f; l[r] = 0.f;
    }

    for (int kt = 0; kt < Sc / KT; ++kt) {
        __syncthreads();   // all warps done reading sK/sV of prior iter

        const float* kb = kb0 + (size_t)kt * KT * Dc;
        const float* vb = vb0 + (size_t)kt * KT * Dc;
#pragma unroll
        for (int it = 0; it < 8; ++it) {
            int idx = tid + it * NT;
            int krow = idx >> 4, c4 = (idx & 15) << 2;
            float4 kv = *(const float4*)(kb + krow * Dc + c4);
            int kg = krow >> 2, ko = krow & 3;
#pragma unroll
            for (int i = 0; i < 4; ++i) {
                int d = c4 + i;
                int pg = kg ^ ((d >> 2) & 15);     // swizzle (low 4 bits only)
                sK[d * KT + (pg << 2) + ko] = f4c(kv, i);
            }
            float4 vv = *(const float4*)(vb + krow * Dc + c4);
            *(float4*)&sV[krow * Dc + c4] = vv;
        }
        __syncthreads();

        // ---- S = (8Q) K^T, 8x8 per thread, f32x2 packed over k-pairs ----
        u64 c2[8][4];
#pragma unroll
        for (int r = 0; r < 8; ++r)
#pragma unroll
            for (int j = 0; j < 4; ++j) c2[r][j] = 0ull;

#pragma unroll 4
        for (int d4 = 0; d4 < 64; d4 += 4) {
            float4 a[8];
#pragma unroll
            for (int r = 0; r < 8; ++r)
                a[r] = *(const float4*)&sQ[(rowb + r) * Dc + d4];
            const int g0 = ((tx ^ ((d4 >> 2) & 15)) << 2);
#pragma unroll
            for (int t = 0; t < 4; ++t) {
                const ulonglong2 b0 = *(const ulonglong2*)&sK[(d4 + t) * KT + g0];
                const ulonglong2 b1 = *(const ulonglong2*)&sK[(d4 + t) * KT + 64 + g0];
#pragma unroll
                for (int r = 0; r < 8; ++r) {
                    u64 ad = dup2(f4c(a[r], t));
                    fma2(c2[r][0], ad, b0.x);
                    fma2(c2[r][1], ad, b0.y);
                    fma2(c2[r][2], ad, b1.x);
                    fma2(c2[r][3], ad, b1.y);
                }
            }
        }

        // ---- online softmax + dropout; exp gated, reductions use half-mask ----
        int anykept = 0;
#pragma unroll
        for (int r = 0; r < 8; ++r) {
            float s8[8];
            unpack2(c2[r][0], s8[0], s8[1]);
            unpack2(c2[r][1], s8[2], s8[3]);
            unpack2(c2[r][2], s8[4], s8[5]);
            unpack2(c2[r][3], s8[6], s8[7]);
            float tm8 = fmaxf(fmaxf(fmaxf(s8[0], s8[1]), fmaxf(s8[2], s8[3])),
                              fmaxf(fmaxf(s8[4], s8[5]), fmaxf(s8[6], s8[7])));
            float tm = tm8;
            // convergent execution: 16-lane max reduction (legal with hm too)
#pragma unroll
            for (int s = 1; s < 16; s <<= 1)
                tm = fmaxf(tm, __shfl_xor_sync(hm, tm, s));

            if (tm > m[r] - 28.f) {              // uniform within 16-lane half
                float mn = fmaxf(m[r], tm);
                float alpha = __expf(m[r] - mn);
                float rs = 0.f;
                if (tm8 > mn - 28.f) {           // this thread's chunk significant
#pragma unroll
                    for (int j = 0; j < 8; ++j) {
                        float e = __expf(s8[j] - mn);
                        s8[j] = e; rs += e;
                    }
                } else {
#pragma unroll
                    for (int j = 0; j < 8; ++j) s8[j] = 0.f;
                }
                // divergent region: MUST use the 16-lane member mask
#pragma unroll
                for (int s = 1; s < 16; s <<= 1)
                    rs += __shfl_xor_sync(hm, rs, s);
                l[r] = l[r] * alpha + rs;
                m[r] = mn;
                u64 a2 = dup2(alpha);
                o2[r][0] = mul2(o2[r][0], a2);
                o2[r][1] = mul2(o2[r][1], a2);

                // dropout: threefry only for survivors (~5 per full row)
                uint32_t gqr = (uint32_t)(q0 + rowb + r);
#pragma unroll
                for (int j = 0; j < 8; ++j) {
                    float p = s8[j];
                    float op = 0.f;
                    if (p > 1e-12f) {
                        uint32_t gkc = (uint32_t)(kt * KT +
                            ((j < 4) ? (tx * 4 + j) : (64 + tx * 4 + (j - 4))));
                        if (keep_mask(bh, gqr, gkc)) { op = p * 10.f; anykept = 1; }
                    }
                    s8[j] = op;
                }
            } else {
#pragma unroll
                for (int j = 0; j < 8; ++j) s8[j] = 0.f;
            }
            // always store P row (zeros if insignificant) — warp-private slab
            *(float4*)&sP[(rowb + r) * KT + (tx << 2)] =
                make_float4(s8[0], s8[1], s8[2], s8[3]);
            *(float4*)&sP[(rowb + r) * KT + 64 + (tx << 2)] =
                make_float4(s8[4], s8[5], s8[6], s8[7]);
        }
        __syncwarp();

        // ---- per-warp exact PV skip (convergent full-warp vote) ----
        if (__any_sync(0xffffffffu, anykept)) {
#pragma unroll 2
            for (int k4 = 0; k4 < KT; k4 += 4) {
                float4 pa[8];
#pragma unroll
                for (int r = 0; r < 8; ++r)
                    pa[r] = *(const float4*)&sP[(rowb + r) * KT + k4];
#pragma unroll
                for (int t = 0; t < 4; ++t) {
                    const ulonglong2 vb2 =
                        *(const ulonglong2*)&sV[(k4 + t) * Dc + (tx << 2)];
#pragma unroll
                    for (int r = 0; r < 8; ++r) {
                        u64 ad = dup2(f4c(pa[r], t));
                        fma2(o2[r][0], ad, vb2.x);
                        fma2(o2[r][1], ad, vb2.y);
                    }
                }
            }
        }
    }

    // ---- epilogue ----
    float* ob = gout + ((size_t)bh * Sc + q0) * Dc;
#pragma unroll
    for (int r = 0; r < 8; ++r) {
        float il = 1.0f / l[r];
        float x0, x1, x2, x3;
        unpack2(o2[r][0], x0, x1);
        unpack2(o2[r][1], x2, x3);
        *(float4*)&ob[(rowb + r) * Dc + (tx << 2)] =
            make_float4(x0 * il, x1 * il, x2 * il, x3 * il);
    }
}

extern "C" void kernel_launch(void* const* d_in, const int* in_sizes, int n_in,
                              void* d_out, int out_size)
{
    (void)in_sizes; (void)n_in; (void)out_size;
    const float* q = (const float*)d_in[0];
    const float* k = (const float*)d_in[1];
    const float* v = (const float*)d_in[2];
    float* o = (float*)d_out;

    size_t smem = SMEM_FLOATS * sizeof(float);   // 163840 B
    cudaFuncSetAttribute(attn_kernel,
                         cudaFuncAttributeMaxDynamicSharedMemorySize, (int)smem);
    dim3 grid(Sc / QT, Bc * Hc);
    attn_kernel<<<grid, NT, smem>>>(q, k, v, o);
}

// round 7
// speedup vs baseline: 2.7868x; 2.7868x over previous
#include <cuda_runtime.h>
#include <cuda_bf16.h>
#include <cstdint>

static constexpr int Sc = 2048, Dc = 64;

// fragment buffers: Q A-frags (scaled by 8, split hi/lo), K B-frags (split)
// Q: ((bh*128+blk)*2+sp)*4+ks -> [lane] uint4(a0,a1,a2,a3)
// K: ((bh*256+cbg)*2+sp)*2+kp -> [lane] uint4(ks_even b0,b1, ks_odd b0,b1)
__device__ uint4 g_qfrag[64 * 128 * 2 * 4 * 32];
__device__ uint4 g_kfrag[64 * 256 * 2 * 2 * 32];

// ---------------- threefry dropout (verified): keep = (x0^x1)>>9 < 838861 ---
__device__ __forceinline__ void threefry2x32(uint32_t c0, uint32_t c1,
                                             uint32_t& o0, uint32_t& o1)
{
    const uint32_t K0 = 0u, K1 = 42u, K2 = 0x1BD11BDAu ^ K0 ^ K1;
    uint32_t x0 = c0 + K0, x1 = c1 + K1;
#define TF_R(r) { x0 += x1; x1 = __funnelshift_l(x1, x1, (r)); x1 ^= x0; }
    TF_R(13) TF_R(15) TF_R(26) TF_R(6)  x0 += K1; x1 += K2 + 1u;
    TF_R(17) TF_R(29) TF_R(16) TF_R(24) x0 += K2; x1 += K0 + 2u;
    TF_R(13) TF_R(15) TF_R(26) TF_R(6)  x0 += K0; x1 += K1 + 3u;
    TF_R(17) TF_R(29) TF_R(16) TF_R(24) x0 += K1; x1 += K2 + 4u;
    TF_R(13) TF_R(15) TF_R(26) TF_R(6)  x0 += K2; x1 += K0 + 5u;
#undef TF_R
    o0 = x0; o1 = x1;
}
__device__ __forceinline__ bool keep_mask(uint32_t bh, uint32_t gq, uint32_t gk)
{
    uint32_t i = (bh << 22) | (gq << 11) | gk, b0, b1;
    threefry2x32(0u, i, b0, b1);
    return ((b0 ^ b1) >> 9) < 838861u;
}

// ---------------- bf16 helpers ----------------------------------------------
__device__ __forceinline__ uint32_t pk_bf16(float lo, float hi)
{ uint32_t r; asm("cvt.rn.bf16x2.f32 %0, %1, %2;" : "=r"(r) : "f"(hi), "f"(lo)); return r; }

// pack split (sp=0: hi parts, sp=1: lo residuals) of (x,y), pre-scaled inputs
__device__ __forceinline__ uint32_t pk_split(float x, float y, int sp)
{
    float xh = __bfloat162float(__float2bfloat16(x));
    float yh = __bfloat162float(__float2bfloat16(y));
    return sp ? pk_bf16(x - xh, y - yh) : pk_bf16(xh, yh);
}

// ---------------- HMMA m16n8k16 bf16 (baseline PTX, sm_80+) -----------------
__device__ __forceinline__ void mma16816(float& c0, float& c1, float& c2, float& c3,
                                         uint32_t a0, uint32_t a1, uint32_t a2, uint32_t a3,
                                         uint32_t b0, uint32_t b1)
{
    asm volatile("mma.sync.aligned.m16n8k16.row.col.f32.bf16.bf16.f32 "
                 "{%0,%1,%2,%3}, {%4,%5,%6,%7}, {%8,%9}, {%0,%1,%2,%3};"
                 : "+f"(c0), "+f"(c1), "+f"(c2), "+f"(c3)
                 : "r"(a0), "r"(a1), "r"(a2), "r"(a3), "r"(b0), "r"(b1));
}

// ---------------- pre-pass: build fragment buffers --------------------------
__global__ void __launch_bounds__(256)
prepass_kernel(const float* __restrict__ q, const float* __restrict__ k)
{
    int gw = (blockIdx.x * 256 + threadIdx.x) >> 5;
    int lane = threadIdx.x & 31;
    if (gw < 64 * 128 * 2 * 4) {
        // Q A-frag: gw = ((bh*128+blk)*2+sp)*4+ks
        int ks = gw & 3, sp = (gw >> 2) & 1, blk = (gw >> 3) & 127, bh = gw >> 10;
        int r0 = blk * 16 + (lane >> 2);
        int kb = ks * 16 + (lane & 3) * 2;
        const float* qb = q + ((size_t)bh * Sc) * Dc;
        float2 p00 = *(const float2*)(qb + (size_t)r0 * Dc + kb);
        float2 p10 = *(const float2*)(qb + (size_t)(r0 + 8) * Dc + kb);
        float2 p01 = *(const float2*)(qb + (size_t)r0 * Dc + kb + 8);
        float2 p11 = *(const float2*)(qb + (size_t)(r0 + 8) * Dc + kb + 8);
        uint4 o;
        o.x = pk_split(p00.x * 8.f, p00.y * 8.f, sp);   // a0a1: (row, k..k+1)
        o.y = pk_split(p10.x * 8.f, p10.y * 8.f, sp);   // a2a3: (row+8)
        o.z = pk_split(p01.x * 8.f, p01.y * 8.f, sp);   // a4a5: (row, k+8..9)
        o.w = pk_split(p11.x * 8.f, p11.y * 8.f, sp);   // a6a7: (row+8, k+8..9)
        g_qfrag[(size_t)gw * 32 + lane] = o;
    } else {
        // K B-frag: w2 = ((bh*256+cbg)*2+sp)*2+kp
        int w2 = gw - 64 * 128 * 2 * 4;
        int kp = w2 & 1, sp = (w2 >> 1) & 1, cbg = (w2 >> 2) & 255, bh = w2 >> 10;
        int n = cbg * 8 + (lane >> 2);
        const float* kr = k + ((size_t)bh * Sc + n) * Dc;
        uint4 o;
        int k0 = (kp * 2) * 16 + (lane & 3) * 2;
        o.x = pk_split(kr[k0], kr[k0 + 1], sp);
        o.y = pk_split(kr[k0 + 8], kr[k0 + 9], sp);
        int k1 = (kp * 2 + 1) * 16 + (lane & 3) * 2;
        o.z = pk_split(kr[k1], kr[k1 + 1], sp);
        o.w = pk_split(kr[k1 + 8], kr[k1 + 9], sp);
        g_kfrag[(size_t)w2 * 32 + lane] = o;
    }
}

// ---------------- main attention kernel -------------------------------------
__global__ void __launch_bounds__(256, 2)
attn_main(const float* __restrict__ gv, float* __restrict__ gout)
{
    __shared__ uint4 sK4[2048];   // 32 KB: one K-frag tile
    const int tid = threadIdx.x, w = tid >> 5, lane = tid & 31;
    const uint32_t bh = blockIdx.y;
    const int q0 = blockIdx.x * 128;
    const int blk = blockIdx.x * 8 + w;

    // load my A fragments (held for whole kernel)
    uint4 A[2][4];
    {
        const uint4* qf = g_qfrag + ((size_t)(bh * 128 + blk) * 2) * 4 * 32;
#pragma unroll
        for (int sp = 0; sp < 2; ++sp)
#pragma unroll
            for (int ks = 0; ks < 4; ++ks)
                A[sp][ks] = qf[(sp * 4 + ks) * 32 + lane];
    }

    float O[2][16];
#pragma unroll
    for (int r = 0; r < 2; ++r)
#pragma unroll
        for (int c = 0; c < 16; ++c) O[r][c] = 0.f;
    float m0 = -1e30f, m1 = -1e30f, l0 = 0.f, l1 = 0.f;

    const uint32_t gq0 = (uint32_t)(q0 + w * 16 + (lane >> 2));
    const float* vb = gv + (size_t)bh * Sc * Dc;

    for (int kt = 0; kt < 16; ++kt) {
        __syncthreads();
        {
            const uint4* kf = g_kfrag + (size_t)(bh * 16 + kt) * 2048;
#pragma unroll
            for (int i = 0; i < 8; ++i)
                sK4[tid + 256 * i] = kf[tid + 256 * i];
        }
        __syncthreads();

#pragma unroll 1
        for (int cb = 0; cb < 16; ++cb) {
            uint4 B[2][2];
#pragma unroll
            for (int sb = 0; sb < 2; ++sb)
#pragma unroll
                for (int kp = 0; kp < 2; ++kp)
                    B[sb][kp] = sK4[((cb * 2 + sb) * 2 + kp) * 32 + lane];

            float c0 = 0.f, c1 = 0.f, c2 = 0.f, c3 = 0.f;
#pragma unroll
            for (int pr = 0; pr < 4; ++pr) {
                const int sa = pr & 1, sb = pr >> 1;
#pragma unroll
                for (int ks = 0; ks < 4; ++ks) {
                    uint32_t b0 = (ks & 1) ? B[sb][ks >> 1].z : B[sb][ks >> 1].x;
                    uint32_t b1 = (ks & 1) ? B[sb][ks >> 1].w : B[sb][ks >> 1].y;
                    mma16816(c0, c1, c2, c3,
                             A[sa][ks].x, A[sa][ks].y, A[sa][ks].z, A[sa][ks].w,
                             b0, b1);
                }
            }

            // ---- scan: quad row max (lanes of a quad share rows) ----
            float rm0 = fmaxf(c0, c1), rm1 = fmaxf(c2, c3);
            rm0 = fmaxf(rm0, __shfl_xor_sync(0xffffffffu, rm0, 1));
            rm0 = fmaxf(rm0, __shfl_xor_sync(0xffffffffu, rm0, 2));
            rm1 = fmaxf(rm1, __shfl_xor_sync(0xffffffffu, rm1, 1));
            rm1 = fmaxf(rm1, __shfl_xor_sync(0xffffffffu, rm1, 2));

            bool sv[4] = {false, false, false, false};
            float p10[4] = {0.f, 0.f, 0.f, 0.f};
            const int gk0 = kt * 128 + cb * 8 + (lane & 3) * 2;

            if (rm0 > m0 - 28.f) {
                float mn = fmaxf(m0, rm0);
                if (mn > m0) {
                    float al = __expf(m0 - mn);
                    l0 *= al;
#pragma unroll
                    for (int c = 0; c < 16; ++c) O[0][c] *= al;
                    m0 = mn;
                }
                float e0 = (c0 > mn - 28.f) ? __expf(c0 - mn) : 0.f;
                float e1 = (c1 > mn - 28.f) ? __expf(c1 - mn) : 0.f;
                l0 += e0 + e1;
                if (e0 > 1e-12f && keep_mask(bh, gq0, gk0))     { sv[0] = true; p10[0] = e0 * 10.f; }
                if (e1 > 1e-12f && keep_mask(bh, gq0, gk0 + 1)) { sv[1] = true; p10[1] = e1 * 10.f; }
            }
            if (rm1 > m1 - 28.f) {
                float mn = fmaxf(m1, rm1);
                if (mn > m1) {
                    float al = __expf(m1 - mn);
                    l1 *= al;
#pragma unroll
                    for (int c = 0; c < 16; ++c) O[1][c] *= al;
                    m1 = mn;
                }
                float e2 = (c2 > mn - 28.f) ? __expf(c2 - mn) : 0.f;
                float e3 = (c3 > mn - 28.f) ? __expf(c3 - mn) : 0.f;
                l1 += e2 + e3;
                if (e2 > 1e-12f && keep_mask(bh, gq0 + 8, gk0))     { sv[2] = true; p10[2] = e2 * 10.f; }
                if (e3 > 1e-12f && keep_mask(bh, gq0 + 8, gk0 + 1)) { sv[3] = true; p10[3] = e3 * 10.f; }
            }

            // ---- sparse PV apply (survivors are rare) ----
            if (__ballot_sync(0xffffffffu, sv[0] | sv[1] | sv[2] | sv[3])) {
#pragma unroll
                for (int pos = 0; pos < 4; ++pos) {
                    unsigned mk = __ballot_sync(0xffffffffu, sv[pos]);
                    while (mk) {
                        int src = __ffs(mk) - 1;
                        mk &= mk - 1;
                        int gkb   = __shfl_sync(0xffffffffu, gk0 + (pos & 1), src);
                        float pb  = __shfl_sync(0xffffffffu, p10[pos], src);
                        if ((lane >> 2) == (src >> 2)) {
                            const float* vc = vb + (size_t)gkb * Dc + (lane & 3) * 16;
                            float* Or = O[pos >> 1];
#pragma unroll
                            for (int c = 0; c < 4; ++c) {
                                float4 vv = *(const float4*)(vc + 4 * c);
                                Or[4 * c + 0] = fmaf(pb, vv.x, Or[4 * c + 0]);
                                Or[4 * c + 1] = fmaf(pb, vv.y, Or[4 * c + 1]);
                                Or[4 * c + 2] = fmaf(pb, vv.z, Or[4 * c + 2]);
                                Or[4 * c + 3] = fmaf(pb, vv.w, Or[4 * c + 3]);
                            }
                        }
                    }
                }
            }
        }
    }

    // ---- epilogue: quad-sum l, normalize, store ----
    l0 += __shfl_xor_sync(0xffffffffu, l0, 1);
    l0 += __shfl_xor_sync(0xffffffffu, l0, 2);
    l1 += __shfl_xor_sync(0xffffffffu, l1, 1);
    l1 += __shfl_xor_sync(0xffffffffu, l1, 2);
    float il0 = 1.0f / l0, il1 = 1.0f / l1;

    const int gr0 = q0 + w * 16 + (lane >> 2);
    float* o0 = gout + ((size_t)bh * Sc + gr0) * Dc + (lane & 3) * 16;
    float* o1 = gout + ((size_t)bh * Sc + gr0 + 8) * Dc + (lane & 3) * 16;
#pragma unroll
    for (int c = 0; c < 4; ++c) {
        *(float4*)(o0 + 4 * c) = make_float4(O[0][4*c] * il0, O[0][4*c+1] * il0,
                                             O[0][4*c+2] * il0, O[0][4*c+3] * il0);
        *(float4*)(o1 + 4 * c) = make_float4(O[1][4*c] * il1, O[1][4*c+1] * il1,
                                             O[1][4*c+2] * il1, O[1][4*c+3] * il1);
    }
}

extern "C" void kernel_launch(void* const* d_in, const int* in_sizes, int n_in,
                              void* d_out, int out_size)
{
    (void)in_sizes; (void)n_in; (void)out_size;
    const float* q = (const float*)d_in[0];
    const float* k = (const float*)d_in[1];
    const float* v = (const float*)d_in[2];
    float* o = (float*)d_out;

    // pre-pass: 131072 warps total (Q frags then K frags)
    prepass_kernel<<<16384, 256>>>(q, k);
    dim3 grid(Sc / 128, 64);
    attn_main<<<grid, 256>>>(v, o);
}